// round 1
// baseline (speedup 1.0000x reference)
#include <cuda_runtime.h>

// QNN: 4-qubit RY/CNOT circuit sim per sample + linear head + softmax.
// One thread per sample; 16-float state lives in registers.
// Inputs: x [B,4] f32, quantum_weights [3,4] f32, W [6,4] f32, b [6] f32.
// Output: softmax probs [B,6] f32.

#define NQ 4
#define DIM 16

__global__ __launch_bounds__(256) void qnn_kernel(
    const float4* __restrict__ x,     // [B] rows of 4 angles
    const float*  __restrict__ qw,    // [12] trainable angles (3 layers x 4 qubits)
    const float*  __restrict__ W,     // [24] = [6,4]
    const float*  __restrict__ bias,  // [6]
    float2*       __restrict__ out,   // [B*3] (== [B,6] f32)
    int B)
{
    __shared__ float cw[12], sw[12];  // cos/sin of trainable half-angles (uniform)
    __shared__ float Ws[24], bs[6];

    int t = threadIdx.x;
    if (t < 12) __sincosf(0.5f * qw[t], &sw[t], &cw[t]);
    if (t < 24) Ws[t] = W[t];
    if (t < 6)  bs[t] = bias[t];
    __syncthreads();

    int i = blockIdx.x * blockDim.x + t;
    if (i >= B) return;

    // ---- data encoding: |psi> = RY(x0)|0> x RY(x1)|0> x RY(x2)|0> x RY(x3)|0>
    float4 xv = x[i];
    float c0, s0, c1, s1, c2, s2, c3, s3;
    __sincosf(0.5f * xv.x, &s0, &c0);
    __sincosf(0.5f * xv.y, &s1, &c1);
    __sincosf(0.5f * xv.z, &s2, &c2);
    __sincosf(0.5f * xv.w, &s3, &c3);

    // index bit for qubit q is (idx >> (3-q)) & 1  (wire 0 most significant)
    float p01[4], p23[4];
    p01[0] = c0 * c1; p01[1] = c0 * s1; p01[2] = s0 * c1; p01[3] = s0 * s1;
    p23[0] = c2 * c3; p23[1] = c2 * s3; p23[2] = s2 * c3; p23[3] = s2 * s3;

    float st[DIM];
    #pragma unroll
    for (int a = 0; a < 4; a++)
        #pragma unroll
        for (int d = 0; d < 4; d++)
            st[a * 4 + d] = p01[a] * p23[d];

    // ---- 3 layers of trainable RYs, ring CNOTs after layers 0,1
    #pragma unroll
    for (int layer = 0; layer < 3; layer++) {
        #pragma unroll
        for (int q = 0; q < NQ; q++) {
            float cc = cw[layer * 4 + q];
            float ss = sw[layer * 4 + q];
            const int mask = 1 << (3 - q);
            #pragma unroll
            for (int idx = 0; idx < DIM; idx++) {
                if ((idx & mask) == 0) {
                    float a0 = st[idx];
                    float a1 = st[idx | mask];
                    st[idx]        = cc * a0 - ss * a1;
                    st[idx | mask] = ss * a0 + cc * a1;
                }
            }
        }
        if (layer < 2) {
            // ring CNOTs: (0,1),(1,2),(2,3),(3,0) — pure register swaps
            #pragma unroll
            for (int e = 0; e < NQ; e++) {
                const int cq = e, tq = (e + 1) & 3;
                const int mc = 1 << (3 - cq);
                const int mt = 1 << (3 - tq);
                #pragma unroll
                for (int idx = 0; idx < DIM; idx++) {
                    if ((idx & mc) && !(idx & mt)) {
                        float tmp = st[idx];
                        st[idx] = st[idx | mt];
                        st[idx | mt] = tmp;
                    }
                }
            }
        }
    }

    // ---- <Z_q> = sum_i |st[i]|^2 * (bit_q(i) ? -1 : +1)
    float p[DIM];
    #pragma unroll
    for (int idx = 0; idx < DIM; idx++) p[idx] = st[idx] * st[idx];

    float z[NQ];
    #pragma unroll
    for (int q = 0; q < NQ; q++) {
        const int mask = 1 << (3 - q);
        float acc = 0.f;
        #pragma unroll
        for (int idx = 0; idx < DIM; idx++)
            acc += (idx & mask) ? -p[idx] : p[idx];
        z[q] = acc;
    }

    // ---- linear head + softmax over 6
    float l[6];
    #pragma unroll
    for (int k = 0; k < 6; k++) {
        float acc = bs[k];
        #pragma unroll
        for (int q = 0; q < NQ; q++) acc = fmaf(Ws[k * 4 + q], z[q], acc);
        l[k] = acc;
    }
    float m = l[0];
    #pragma unroll
    for (int k = 1; k < 6; k++) m = fmaxf(m, l[k]);
    float e[6], ssum = 0.f;
    #pragma unroll
    for (int k = 0; k < 6; k++) { e[k] = __expf(l[k] - m); ssum += e[k]; }
    float inv = __frcp_rn(ssum);

    out[i * 3 + 0] = make_float2(e[0] * inv, e[1] * inv);
    out[i * 3 + 1] = make_float2(e[2] * inv, e[3] * inv);
    out[i * 3 + 2] = make_float2(e[4] * inv, e[5] * inv);
}

extern "C" void kernel_launch(void* const* d_in, const int* in_sizes, int n_in,
                              void* d_out, int out_size) {
    const float4* x  = (const float4*)d_in[0];
    const float*  qw = (const float*)d_in[1];
    const float*  W  = (const float*)d_in[2];
    const float*  b  = (const float*)d_in[3];
    float2* out = (float2*)d_out;
    int B = in_sizes[0] / 4;
    int threads = 256;
    int blocks = (B + threads - 1) / threads;
    qnn_kernel<<<blocks, threads>>>(x, qw, W, b, out, B);
}